// round 1
// baseline (speedup 1.0000x reference)
#include <cuda_runtime.h>
#include <cuda_bf16.h>
#include <math.h>

// Problem constants
#define BB 64
#define SS 512
#define II 512
#define HH 512
#define LL 2
#define MROWS (BB * LL)          // 128 recurrence rows
#define MX (BB * SS)             // 32768 rows of xa GEMM

// ---------------- scratch (static device memory; no allocs allowed) ----------
__device__ float g_xa[(size_t)MX * HH];       // 64 MB: xa = x @ W_ih^T + b_ih
__device__ float g_h[2][MROWS * HH];          // double-buffered recurrent state
__device__ unsigned g_bar_count = 0;          // global barrier (returns to 0)
__device__ unsigned g_bar_sense = 0;          // toggled 512 times -> back to 0

// =============================================================================
// Kernel A: xa[m][n] = sum_k x[m][k] * W_ih[n][k] + b_ih[n]
// 128x128 tile, BK=8, double buffered, 8x8 per thread, 256 threads.
// =============================================================================
__global__ void __launch_bounds__(256) gemm_xa_kernel(
    const float* __restrict__ A,      // [MX][II]
    const float* __restrict__ Bw,     // [HH][II]
    const float* __restrict__ bias)   // [HH]
{
    __shared__ float As[2][8][128];
    __shared__ float Bs[2][8][128];

    const int K = II;
    const int N = HH;
    const int m0 = blockIdx.y * 128;
    const int n0 = blockIdx.x * 128;
    const int tid = threadIdx.x;
    const int tx = tid & 15;       // 0..15 -> 8 columns each
    const int ty = tid >> 4;       // 0..15 -> 8 rows each
    const int lrow = tid >> 1;     // 0..127
    const int lkq  = (tid & 1) * 4;

    const float* Aptr = A + (size_t)(m0 + lrow) * K + lkq;
    const float* Bptr = Bw + (size_t)(n0 + lrow) * K + lkq;

    float acc[8][8];
#pragma unroll
    for (int i = 0; i < 8; i++)
#pragma unroll
        for (int j = 0; j < 8; j++) acc[i][j] = 0.f;

    // preload tile 0
    {
        float4 av = *(const float4*)Aptr;
        float4 bv = *(const float4*)Bptr;
        As[0][lkq + 0][lrow] = av.x; As[0][lkq + 1][lrow] = av.y;
        As[0][lkq + 2][lrow] = av.z; As[0][lkq + 3][lrow] = av.w;
        Bs[0][lkq + 0][lrow] = bv.x; Bs[0][lkq + 1][lrow] = bv.y;
        Bs[0][lkq + 2][lrow] = bv.z; Bs[0][lkq + 3][lrow] = bv.w;
    }
    __syncthreads();

    for (int kb = 8; kb <= K; kb += 8) {
        const int buf = ((kb >> 3) & 1) ^ 1;   // buffer being computed
        float4 av2, bv2;
        const bool more = (kb < K);
        if (more) {
            av2 = *(const float4*)(Aptr + kb);
            bv2 = *(const float4*)(Bptr + kb);
        }
#pragma unroll
        for (int kk = 0; kk < 8; kk++) {
            float a[8], b[8];
            *(float4*)(a + 0) = *(const float4*)&As[buf][kk][ty * 8 + 0];
            *(float4*)(a + 4) = *(const float4*)&As[buf][kk][ty * 8 + 4];
            *(float4*)(b + 0) = *(const float4*)&Bs[buf][kk][tx * 8 + 0];
            *(float4*)(b + 4) = *(const float4*)&Bs[buf][kk][tx * 8 + 4];
#pragma unroll
            for (int i = 0; i < 8; i++)
#pragma unroll
                for (int j = 0; j < 8; j++)
                    acc[i][j] += a[i] * b[j];
        }
        if (more) {
            const int nb = buf ^ 1;
            As[nb][lkq + 0][lrow] = av2.x; As[nb][lkq + 1][lrow] = av2.y;
            As[nb][lkq + 2][lrow] = av2.z; As[nb][lkq + 3][lrow] = av2.w;
            Bs[nb][lkq + 0][lrow] = bv2.x; Bs[nb][lkq + 1][lrow] = bv2.y;
            Bs[nb][lkq + 2][lrow] = bv2.z; Bs[nb][lkq + 3][lrow] = bv2.w;
            __syncthreads();
        }
    }

    // epilogue: add bias, store float4
    float4 bv0 = *(const float4*)&bias[n0 + tx * 8 + 0];
    float4 bv1 = *(const float4*)&bias[n0 + tx * 8 + 4];
#pragma unroll
    for (int i = 0; i < 8; i++) {
        float* Crow = g_xa + (size_t)(m0 + ty * 8 + i) * N + n0 + tx * 8;
        float4 c0, c1;
        c0.x = acc[i][0] + bv0.x; c0.y = acc[i][1] + bv0.y;
        c0.z = acc[i][2] + bv0.z; c0.w = acc[i][3] + bv0.w;
        c1.x = acc[i][4] + bv1.x; c1.y = acc[i][5] + bv1.y;
        c1.z = acc[i][6] + bv1.z; c1.w = acc[i][7] + bv1.w;
        *(float4*)(Crow + 0) = c0;
        *(float4*)(Crow + 4) = c1;
    }
}

// =============================================================================
// Kernel B: persistent recurrence.
// 128 CTAs (all co-resident), 128 threads (4 warps).
// CTA (rb, gb): rows rb*16..rb*16+15, columns gb*32..gb*32+31.
// W^T slice [512][32] stays in SMEM for all 512 steps.
// warp w: rows w*4..w*4+3 (local); lane = column.
// =============================================================================
#define GB_CTAS 128

__device__ __forceinline__ void global_barrier(unsigned& sense)
{
    __threadfence();                 // publish this thread's writes gpu-wide
    __syncthreads();
    if (threadIdx.x == 0) {
        unsigned t = atomicAdd(&g_bar_count, 1u);
        if (t == GB_CTAS - 1) {
            atomicExch(&g_bar_count, 0u);
            __threadfence();
            atomicExch(&g_bar_sense, sense ^ 1u);   // release
        } else {
            unsigned v;
            do {
                asm volatile("ld.acquire.gpu.u32 %0, [%1];"
                             : "=r"(v) : "l"(&g_bar_sense));
            } while (v == sense);
        }
    }
    __syncthreads();
    sense ^= 1u;
}

__global__ void __launch_bounds__(128, 1) rnn_persistent_kernel(
    const float* __restrict__ W_hh,   // [HH][HH]
    const float* __restrict__ b_hh,   // [HH]
    float* __restrict__ out)          // y then h_last
{
    extern __shared__ float sm[];
    float* Wt = sm;                   // [512][32]  Wt[k][g] = W_hh[g][k]
    float* hs = sm + 512 * 32;        // [16][512]
    float* xs = hs + 16 * 512;        // [8][32]

    const int tid  = threadIdx.x;
    const int lane = tid & 31;
    const int w    = tid >> 5;        // warp 0..3
    const int gb   = blockIdx.x & 15; // 16 g-blocks
    const int rb   = blockIdx.x >> 4; // 8 row-blocks
    const int g    = gb * 32 + lane;  // global column

    // Load W^T slice once (reused for 512 steps)
    for (int idx = tid; idx < 32 * 512; idx += 128) {
        int gg = idx >> 9;
        int k  = idx & 511;
        Wt[k * 32 + gg] = W_hh[(size_t)(gb * 32 + gg) * HH + k];
    }
    const float bg = b_hh[g];
    const int r0 = w * 4;             // local row base of this warp

    unsigned sense = 0;
    __syncthreads();

    const size_t Y_ELEMS = (size_t)BB * SS * LL * HH;   // h_last offset

    for (int s = 0; s < SS; s++) {
        // separates previous step's h writes from this step's reads
        global_barrier(sense);

        // stage h rows for this row-block
        if (s == 0) {
            float4 z = make_float4(0.f, 0.f, 0.f, 0.f);
            float4* dst = (float4*)hs;
            for (int i = tid; i < (16 * 512) / 4; i += 128) dst[i] = z;
        } else {
            const float4* src =
                (const float4*)(&g_h[s & 1][(size_t)rb * 16 * HH]);
            float4* dst = (float4*)hs;
            for (int i = tid; i < (16 * 512) / 4; i += 128)
                dst[i] = __ldcg(src + i);   // bypass (possibly stale) L1
        }
        // stage xa for this step: 8 local batches x 32 columns
        for (int i = tid; i < 256; i += 128) {
            int bl = i >> 5, gg = i & 31;
            xs[i] = g_xa[((size_t)(rb * 8 + bl) * SS + s) * HH + gb * 32 + gg];
        }
        __syncthreads();

        // compute: 4 rows x 1 column per thread, K=512
        const float* h0p = hs + (r0 + 0) * 512;
        const float* h1p = hs + (r0 + 1) * 512;
        const float* h2p = hs + (r0 + 2) * 512;
        const float* h3p = hs + (r0 + 3) * 512;
        float a0 = 0.f, a1 = 0.f, a2 = 0.f, a3 = 0.f;
#pragma unroll 2
        for (int k = 0; k < 512; k += 4) {
            const float4 hv0 = *(const float4*)(h0p + k);
            const float4 hv1 = *(const float4*)(h1p + k);
            const float4 hv2 = *(const float4*)(h2p + k);
            const float4 hv3 = *(const float4*)(h3p + k);
            const float w0 = Wt[(k + 0) * 32 + lane];
            const float w1 = Wt[(k + 1) * 32 + lane];
            const float w2 = Wt[(k + 2) * 32 + lane];
            const float w3 = Wt[(k + 3) * 32 + lane];
            a0 += w0 * hv0.x; a0 += w1 * hv0.y; a0 += w2 * hv0.z; a0 += w3 * hv0.w;
            a1 += w0 * hv1.x; a1 += w1 * hv1.y; a1 += w2 * hv1.z; a1 += w3 * hv1.w;
            a2 += w0 * hv2.x; a2 += w1 * hv2.y; a2 += w2 * hv2.z; a2 += w3 * hv2.w;
            a3 += w0 * hv3.x; a3 += w1 * hv3.y; a3 += w2 * hv3.z; a3 += w3 * hv3.w;
        }

        // activation + writes
        float v0 = tanhf(a0 + xs[((r0 + 0) >> 1) * 32 + lane] + bg);
        float v1 = tanhf(a1 + xs[((r0 + 1) >> 1) * 32 + lane] + bg);
        float v2 = tanhf(a2 + xs[((r0 + 2) >> 1) * 32 + lane] + bg);
        float v3 = tanhf(a3 + xs[((r0 + 3) >> 1) * 32 + lane] + bg);

        float* hn = g_h[(s + 1) & 1];
        const int row0 = rb * 16 + r0;
        hn[(size_t)(row0 + 0) * HH + g] = v0;
        hn[(size_t)(row0 + 1) * HH + g] = v1;
        hn[(size_t)(row0 + 2) * HH + g] = v2;
        hn[(size_t)(row0 + 3) * HH + g] = v3;

#pragma unroll
        for (int j = 0; j < 4; j++) {
            const int row = row0 + j;
            const int b = row >> 1;
            const int l = row & 1;
            const float v = (j == 0) ? v0 : (j == 1) ? v1 : (j == 2) ? v2 : v3;
            out[(((size_t)b * SS + s) * LL + l) * HH + g] = v;
            if (s == SS - 1)
                out[Y_ELEMS + (size_t)row * HH + g] = v;
        }
        __syncthreads();   // all epilogue smem reads done before next stage
    }
}

// =============================================================================
// launch
// =============================================================================
extern "C" void kernel_launch(void* const* d_in, const int* in_sizes, int n_in,
                              void* d_out, int out_size)
{
    const float* x    = (const float*)d_in[0];
    const float* W_ih = (const float*)d_in[1];
    const float* b_ih = (const float*)d_in[2];
    const float* W_hh = (const float*)d_in[3];
    const float* b_hh = (const float*)d_in[4];
    float* out = (float*)d_out;

    // Kernel A: xa = x @ W_ih^T + b_ih
    dim3 gridA(HH / 128, MX / 128);
    gemm_xa_kernel<<<gridA, 256>>>(x, W_ih, b_ih);

    // Kernel B: persistent recurrence
    const int smemB = (512 * 32 + 16 * 512 + 256) * (int)sizeof(float);
    cudaFuncSetAttribute(rnn_persistent_kernel,
                         cudaFuncAttributeMaxDynamicSharedMemorySize, smemB);
    rnn_persistent_kernel<<<GB_CTAS, 128, smemB>>>(W_hh, b_hh, out);
}

// round 3
// speedup vs baseline: 1.1721x; 1.1721x over previous
#include <cuda_runtime.h>
#include <cuda_bf16.h>
#include <math.h>

// Problem constants
#define BB 64
#define SS 512
#define II 512
#define HH 512
#define LL 2
#define MROWS (BB * LL)          // 128 recurrence rows
#define MX (BB * SS)             // 32768 rows of xa GEMM

// ---------------- scratch (static device memory; no allocs allowed) ----------
__device__ float g_xa[(size_t)MX * HH];       // 64 MB: xa = x @ W_ih^T + b_ih
__device__ float g_h[2][MROWS * HH];          // double-buffered recurrent state

// per-row-block barrier state (8 groups of 16 CTAs), 128B padding per entry
#define RB_GROUPS 8
__device__ unsigned g_cnt[RB_GROUPS * 32];    // arrival counts (return to 0)
__device__ unsigned g_sense[RB_GROUPS * 32];  // 512 toggles -> back to 0

// =============================================================================
// Kernel A: xa[m][n] = sum_k x[m][k] * W_ih[n][k] + b_ih[n]
// 128x128 tile, BK=8, double buffered, 8x8 per thread, 256 threads.
// =============================================================================
__global__ void __launch_bounds__(256) gemm_xa_kernel(
    const float* __restrict__ A,      // [MX][II]
    const float* __restrict__ Bw,     // [HH][II]
    const float* __restrict__ bias)   // [HH]
{
    __shared__ float As[2][8][128];
    __shared__ float Bs[2][8][128];

    const int K = II;
    const int N = HH;
    const int m0 = blockIdx.y * 128;
    const int n0 = blockIdx.x * 128;
    const int tid = threadIdx.x;
    const int tx = tid & 15;       // 0..15 -> 8 columns each
    const int ty = tid >> 4;       // 0..15 -> 8 rows each
    const int lrow = tid >> 1;     // 0..127
    const int lkq  = (tid & 1) * 4;

    const float* Aptr = A + (size_t)(m0 + lrow) * K + lkq;
    const float* Bptr = Bw + (size_t)(n0 + lrow) * K + lkq;

    float acc[8][8];
#pragma unroll
    for (int i = 0; i < 8; i++)
#pragma unroll
        for (int j = 0; j < 8; j++) acc[i][j] = 0.f;

    // preload tile 0
    {
        float4 av = *(const float4*)Aptr;
        float4 bv = *(const float4*)Bptr;
        As[0][lkq + 0][lrow] = av.x; As[0][lkq + 1][lrow] = av.y;
        As[0][lkq + 2][lrow] = av.z; As[0][lkq + 3][lrow] = av.w;
        Bs[0][lkq + 0][lrow] = bv.x; Bs[0][lkq + 1][lrow] = bv.y;
        Bs[0][lkq + 2][lrow] = bv.z; Bs[0][lkq + 3][lrow] = bv.w;
    }
    __syncthreads();

    for (int kb = 8; kb <= K; kb += 8) {
        const int buf = ((kb >> 3) & 1) ^ 1;   // buffer being computed
        float4 av2, bv2;
        const bool more = (kb < K);
        if (more) {
            av2 = *(const float4*)(Aptr + kb);
            bv2 = *(const float4*)(Bptr + kb);
        }
#pragma unroll
        for (int kk = 0; kk < 8; kk++) {
            float a[8], b[8];
            *(float4*)(a + 0) = *(const float4*)&As[buf][kk][ty * 8 + 0];
            *(float4*)(a + 4) = *(const float4*)&As[buf][kk][ty * 8 + 4];
            *(float4*)(b + 0) = *(const float4*)&Bs[buf][kk][tx * 8 + 0];
            *(float4*)(b + 4) = *(const float4*)&Bs[buf][kk][tx * 8 + 4];
#pragma unroll
            for (int i = 0; i < 8; i++)
#pragma unroll
                for (int j = 0; j < 8; j++)
                    acc[i][j] += a[i] * b[j];
        }
        if (more) {
            const int nb = buf ^ 1;
            As[nb][lkq + 0][lrow] = av2.x; As[nb][lkq + 1][lrow] = av2.y;
            As[nb][lkq + 2][lrow] = av2.z; As[nb][lkq + 3][lrow] = av2.w;
            Bs[nb][lkq + 0][lrow] = bv2.x; Bs[nb][lkq + 1][lrow] = bv2.y;
            Bs[nb][lkq + 2][lrow] = bv2.z; Bs[nb][lkq + 3][lrow] = bv2.w;
            __syncthreads();
        }
    }

    // epilogue: add bias, store float4
    float4 bv0 = *(const float4*)&bias[n0 + tx * 8 + 0];
    float4 bv1 = *(const float4*)&bias[n0 + tx * 8 + 4];
#pragma unroll
    for (int i = 0; i < 8; i++) {
        float* Crow = g_xa + (size_t)(m0 + ty * 8 + i) * N + n0 + tx * 8;
        float4 c0, c1;
        c0.x = acc[i][0] + bv0.x; c0.y = acc[i][1] + bv0.y;
        c0.z = acc[i][2] + bv0.z; c0.w = acc[i][3] + bv0.w;
        c1.x = acc[i][4] + bv1.x; c1.y = acc[i][5] + bv1.y;
        c1.z = acc[i][6] + bv1.z; c1.w = acc[i][7] + bv1.w;
        *(float4*)(Crow + 0) = c0;
        *(float4*)(Crow + 4) = c1;
    }
}

// =============================================================================
// Kernel B: persistent recurrence.
// 128 CTAs (8 rb x 16 gb), 256 threads (8 warps).
// CTA (rb, gb): rows rb*16..+15, columns gb*32..+31.
// W^T slice [32][516] (padded) resident in SMEM for all 512 steps.
// warp w handles local rows 2w, 2w+1 (same batch index); lane = column.
// Barrier is per-row-block: only the 16 CTAs sharing rb synchronize.
// =============================================================================
#define GB_CTAS 128

__global__ void __launch_bounds__(256, 1) rnn_persistent_kernel(
    const float* __restrict__ W_hh,   // [HH][HH]
    const float* __restrict__ b_hh,   // [HH]
    float* __restrict__ out)          // y then h_last
{
    extern __shared__ float sm[];
    float* Wt = sm;                   // [32][516]  Wt[gg][k] = W_hh[gb*32+gg][k]
    float* hs = sm + 32 * 516;        // [16][512]

    const int tid  = threadIdx.x;
    const int lane = tid & 31;
    const int w    = tid >> 5;        // warp 0..7
    const int gb   = blockIdx.x & 15; // 16 g-blocks
    const int rb   = blockIdx.x >> 4; // 8 row-blocks
    const int g    = gb * 32 + lane;  // global column

    // Load W slice once (reused for 512 steps): Wt[gg][k], row stride 516
    for (int idx = tid; idx < 32 * 512; idx += 256) {
        int gg = idx >> 9;
        int k  = idx & 511;
        Wt[gg * 516 + k] = W_hh[(size_t)(gb * 32 + gg) * HH + k];
    }
    const float bg    = __ldg(&b_hh[g]);
    const int   b_idx = rb * 8 + w;       // batch index for this warp's rows
    const int   row0  = rb * 16 + 2 * w;  // global rows row0 (l=0), row0+1 (l=1)

    unsigned* cnt = &g_cnt[rb * 32];
    unsigned* sns = &g_sense[rb * 32];
    unsigned  sense = 0;

    // prefetch xa for step 0 (depends only on kernel A)
    float xav = __ldg(&g_xa[((size_t)b_idx * SS + 0) * HH + g]);
    __syncthreads();

    const size_t Y_ELEMS = (size_t)BB * SS * LL * HH;   // h_last offset

    for (int s = 0; s < SS; s++) {
        float a0 = 0.f, a1 = 0.f;
        if (s) {
            // wait for group (16 CTAs sharing rb) to finish step s-1
            if (tid == 0) {
                unsigned v;
                do {
                    asm volatile("ld.acquire.gpu.u32 %0, [%1];"
                                 : "=r"(v) : "l"(sns));
                } while (v != sense);
            }
            __syncthreads();

            // stage h rows for this row-block (32 KB) from L2
            const float4* src =
                (const float4*)(&g_h[s & 1][(size_t)rb * 16 * HH]);
            float4* dst = (float4*)hs;
#pragma unroll
            for (int i = 0; i < 8; i++)
                dst[tid + i * 256] = __ldcg(src + tid + i * 256);
            __syncthreads();

            // compute: 2 rows x 1 column per thread, K=512
            const float* h0p = hs + (2 * w + 0) * 512;
            const float* h1p = hs + (2 * w + 1) * 512;
            const float* wp  = Wt + lane * 516;
#pragma unroll 4
            for (int k = 0; k < 512; k += 4) {
                const float4 wv = *(const float4*)(wp + k);
                const float4 h0 = *(const float4*)(h0p + k);
                const float4 h1 = *(const float4*)(h1p + k);
                a0 += wv.x * h0.x; a1 += wv.x * h1.x;
                a0 += wv.y * h0.y; a1 += wv.y * h1.y;
                a0 += wv.z * h0.z; a1 += wv.z * h1.z;
                a0 += wv.w * h0.w; a1 += wv.w * h1.w;
            }
        }

        const float v0 = tanhf(a0 + xav + bg);
        const float v1 = tanhf(a1 + xav + bg);

        // publish h for next step (straight to L2)
        float* hn = g_h[(s + 1) & 1];
        __stcg(&hn[(size_t)(row0 + 0) * HH + g], v0);
        __stcg(&hn[(size_t)(row0 + 1) * HH + g], v1);
        __syncthreads();

        // group barrier arrival (release publishes all threads' h writes)
        if (tid == 0) {
            unsigned old;
            asm volatile("atom.add.release.gpu.u32 %0, [%1], %2;"
                         : "=r"(old) : "l"(cnt), "r"(1u));
            if (old == 15u) {
                asm volatile("st.relaxed.gpu.u32 [%0], %1;"
                             :: "l"(cnt), "r"(0u));
                asm volatile("st.release.gpu.u32 [%0], %1;"
                             :: "l"(sns), "r"(sense ^ 1u));
            }
        }
        sense ^= 1u;

        // epilogue overlaps peers' spin: y writes + xa prefetch
        out[(((size_t)b_idx * SS + s) * LL + 0) * HH + g] = v0;
        out[(((size_t)b_idx * SS + s) * LL + 1) * HH + g] = v1;
        if (s == SS - 1) {
            out[Y_ELEMS + (size_t)(row0 + 0) * HH + g] = v0;
            out[Y_ELEMS + (size_t)(row0 + 1) * HH + g] = v1;
        } else {
            xav = __ldg(&g_xa[((size_t)b_idx * SS + (s + 1)) * HH + g]);
        }
    }
}

// =============================================================================
// launch
// =============================================================================
extern "C" void kernel_launch(void* const* d_in, const int* in_sizes, int n_in,
                              void* d_out, int out_size)
{
    const float* x    = (const float*)d_in[0];
    const float* W_ih = (const float*)d_in[1];
    const float* b_ih = (const float*)d_in[2];
    const float* W_hh = (const float*)d_in[3];
    const float* b_hh = (const float*)d_in[4];
    float* out = (float*)d_out;

    // Kernel A: xa = x @ W_ih^T + b_ih
    dim3 gridA(HH / 128, MX / 128);
    gemm_xa_kernel<<<gridA, 256>>>(x, W_ih, b_ih);

    // Kernel B: persistent recurrence
    const int smemB = (32 * 516 + 16 * 512) * (int)sizeof(float);
    cudaFuncSetAttribute(rnn_persistent_kernel,
                         cudaFuncAttributeMaxDynamicSharedMemorySize, smemB);
    rnn_persistent_kernel<<<GB_CTAS, 256, smemB>>>(W_hh, b_hh, out);
}

// round 5
// speedup vs baseline: 1.6924x; 1.4439x over previous
#include <cuda_runtime.h>
#include <cuda_bf16.h>
#include <math.h>

// Problem constants
#define BB 64
#define SS 512
#define II 512
#define HH 512
#define LL 2
#define MROWS (BB * LL)          // 128 recurrence rows
#define MX (BB * SS)             // 32768 rows of xa GEMM

// ---------------- scratch (static device memory; no allocs allowed) ----------
__device__ float g_xa[(size_t)MX * HH];       // 64 MB: xa = x @ W_ih^T + b_ih
__device__ float g_h[2][MROWS * HH];          // double-buffered recurrent state

// per-row-group barrier state (16 groups of 8 CTAs), padded slots
#define RB_GROUPS 16
__device__ unsigned g_cnt[RB_GROUPS * 32];    // arrival counts (return to 0)
__device__ unsigned g_sense[RB_GROUPS * 32];  // 512 toggles -> back to 0

// =============================================================================
// Kernel A: xa[m][n] = sum_k x[m][k] * W_ih[n][k] + b_ih[n]
// 128x128 tile, BK=8, double buffered, 8x8 per thread, 256 threads.
// =============================================================================
__global__ void __launch_bounds__(256) gemm_xa_kernel(
    const float* __restrict__ A,      // [MX][II]
    const float* __restrict__ Bw,     // [HH][II]
    const float* __restrict__ bias)   // [HH]
{
    __shared__ float As[2][8][128];
    __shared__ float Bs[2][8][128];

    const int K = II;
    const int N = HH;
    const int m0 = blockIdx.y * 128;
    const int n0 = blockIdx.x * 128;
    const int tid = threadIdx.x;
    const int tx = tid & 15;
    const int ty = tid >> 4;
    const int lrow = tid >> 1;
    const int lkq  = (tid & 1) * 4;

    const float* Aptr = A + (size_t)(m0 + lrow) * K + lkq;
    const float* Bptr = Bw + (size_t)(n0 + lrow) * K + lkq;

    float acc[8][8];
#pragma unroll
    for (int i = 0; i < 8; i++)
#pragma unroll
        for (int j = 0; j < 8; j++) acc[i][j] = 0.f;

    {
        float4 av = *(const float4*)Aptr;
        float4 bv = *(const float4*)Bptr;
        As[0][lkq + 0][lrow] = av.x; As[0][lkq + 1][lrow] = av.y;
        As[0][lkq + 2][lrow] = av.z; As[0][lkq + 3][lrow] = av.w;
        Bs[0][lkq + 0][lrow] = bv.x; Bs[0][lkq + 1][lrow] = bv.y;
        Bs[0][lkq + 2][lrow] = bv.z; Bs[0][lkq + 3][lrow] = bv.w;
    }
    __syncthreads();

    for (int kb = 8; kb <= K; kb += 8) {
        const int buf = ((kb >> 3) & 1) ^ 1;
        float4 av2, bv2;
        const bool more = (kb < K);
        if (more) {
            av2 = *(const float4*)(Aptr + kb);
            bv2 = *(const float4*)(Bptr + kb);
        }
#pragma unroll
        for (int kk = 0; kk < 8; kk++) {
            float a[8], b[8];
            *(float4*)(a + 0) = *(const float4*)&As[buf][kk][ty * 8 + 0];
            *(float4*)(a + 4) = *(const float4*)&As[buf][kk][ty * 8 + 4];
            *(float4*)(b + 0) = *(const float4*)&Bs[buf][kk][tx * 8 + 0];
            *(float4*)(b + 4) = *(const float4*)&Bs[buf][kk][tx * 8 + 4];
#pragma unroll
            for (int i = 0; i < 8; i++)
#pragma unroll
                for (int j = 0; j < 8; j++)
                    acc[i][j] += a[i] * b[j];
        }
        if (more) {
            const int nb = buf ^ 1;
            As[nb][lkq + 0][lrow] = av2.x; As[nb][lkq + 1][lrow] = av2.y;
            As[nb][lkq + 2][lrow] = av2.z; As[nb][lkq + 3][lrow] = av2.w;
            Bs[nb][lkq + 0][lrow] = bv2.x; Bs[nb][lkq + 1][lrow] = bv2.y;
            Bs[nb][lkq + 2][lrow] = bv2.z; Bs[nb][lkq + 3][lrow] = bv2.w;
            __syncthreads();
        }
    }

    float4 bv0 = *(const float4*)&bias[n0 + tx * 8 + 0];
    float4 bv1 = *(const float4*)&bias[n0 + tx * 8 + 4];
#pragma unroll
    for (int i = 0; i < 8; i++) {
        float* Crow = g_xa + (size_t)(m0 + ty * 8 + i) * N + n0 + tx * 8;
        float4 c0, c1;
        c0.x = acc[i][0] + bv0.x; c0.y = acc[i][1] + bv0.y;
        c0.z = acc[i][2] + bv0.z; c0.w = acc[i][3] + bv0.w;
        c1.x = acc[i][4] + bv1.x; c1.y = acc[i][5] + bv1.y;
        c1.z = acc[i][6] + bv1.z; c1.w = acc[i][7] + bv1.w;
        *(float4*)(Crow + 0) = c0;
        *(float4*)(Crow + 4) = c1;
    }
}

// =============================================================================
// Kernel B: persistent recurrence, v3.
// 128 CTAs = 16 row-groups (rb) x 8 col-blocks (gb).
// CTA: rows rb*8..+7, cols gb*64..+63, K=512.
// SMEM: Wt[512][64] (col-fast, 128 KB, resident), hs[8][516], red[8][512].
// 256 threads: kq = tid>>5 (K-slice of 64, one per warp),
//              rowg = (tid>>4)&1 (4 rows), colg = tid&15 (4 cols).
// Thread computes a 4x4 tile over its 64-wide K slice (64 FFMA / 8 LDS.128),
// partials reduced over kq through smem. Barrier is per-row-group (8 CTAs).
// =============================================================================
#define GB_CTAS 128
#define GRP 8                      // CTAs per barrier group

__global__ void __launch_bounds__(256, 1) rnn_persistent_kernel(
    const float* __restrict__ W_hh,   // [HH][HH]
    const float* __restrict__ b_hh,   // [HH]
    float* __restrict__ out)          // y then h_last
{
    extern __shared__ float sm[];
    float* Wt  = sm;                   // [512][64]  Wt[k][c] = W_hh[g0+c][k]
    float* hs  = sm + 512 * 64;        // [8][516] (padded)
    float* red = hs + 8 * 516;         // [8 kq][512 outputs]

    const int tid = threadIdx.x;
    const int gb  = blockIdx.x & 7;    // 8 col-blocks
    const int rb  = blockIdx.x >> 3;   // 16 row-groups
    const int g0  = gb * 64;
    const int row_base = rb * 8;

    // ---- one-time: load W slice transposed into smem (col-fast) ----
    {
        const int c  = tid & 63;
        const int k0 = tid >> 6;       // 0..3
        const float* wsrc = W_hh + (size_t)(g0 + c) * HH;
#pragma unroll 8
        for (int k = k0; k < 512; k += 4)
            Wt[k * 64 + c] = __ldg(wsrc + k);
    }

    // ---- compute-role indices ----
    const int kq    = tid >> 5;        // warp id = K-slice
    const int rowg  = (tid >> 4) & 1;
    const int colg  = tid & 15;
    const int kbase = kq * 64;
    const int r0    = rowg * 4;
    const int c0    = colg * 4;

    // ---- epilogue-role indices: outputs o = 2*tid, 2*tid+1 ----
    const int orow  = tid >> 5;        // local row 0..7 (one per warp)
    const int oc    = 2 * (tid & 31);  // local col pair
    const int grow  = row_base + orow; // global recurrence row
    const int b_idx = grow >> 1;       // batch
    const int l_idx = grow & 1;        // layer
    const int gcol  = g0 + oc;         // global column pair base

    const float2 bg  = *(const float2*)&b_hh[gcol];
    float2 xav = *(const float2*)&g_xa[((size_t)b_idx * SS + 0) * HH + gcol];

    unsigned* cnt = &g_cnt[rb * 32];
    unsigned* sns = &g_sense[rb * 32];
    unsigned  sense = 0;

    const size_t Y_ELEMS = (size_t)BB * SS * LL * HH;
    __syncthreads();

    for (int s = 0; s < SS; s++) {
        float v0, v1;
        if (s == 0) {
            v0 = tanhf(xav.x + bg.x);
            v1 = tanhf(xav.y + bg.y);
        } else {
            // wait for group (8 CTAs sharing rb) to finish step s-1
            if (tid == 0) {
                unsigned v;
                do {
                    asm volatile("ld.acquire.gpu.u32 %0, [%1];"
                                 : "=r"(v) : "l"(sns));
                } while (v != sense);
            }
            __syncthreads();

            // stage h rows (8 x 512 = 16 KB) from L2 into padded smem
            const float4* src =
                (const float4*)(&g_h[s & 1][(size_t)row_base * HH]);
#pragma unroll
            for (int j = 0; j < 4; j++) {
                const int idx = tid + j * 256;      // float4 index, 0..1023
                const int r   = idx >> 7;
                const int kk  = idx & 127;
                *(float4*)&hs[r * 516 + kk * 4] = __ldcg(src + idx);
            }
            __syncthreads();

            // compute 4x4 tile over K-slice [kbase, kbase+64)
            float acc[4][4];
#pragma unroll
            for (int i = 0; i < 4; i++)
#pragma unroll
                for (int j = 0; j < 4; j++) acc[i][j] = 0.f;

            const float* hp = hs + r0 * 516 + kbase;
            const float* wp = Wt + kbase * 64 + c0;
#pragma unroll 2
            for (int k = 0; k < 64; k += 4) {
                const float4 w0 = *(const float4*)(wp + (k + 0) * 64);
                const float4 w1 = *(const float4*)(wp + (k + 1) * 64);
                const float4 w2 = *(const float4*)(wp + (k + 2) * 64);
                const float4 w3 = *(const float4*)(wp + (k + 3) * 64);
                const float4 h0 = *(const float4*)(hp + 0 * 516 + k);
                const float4 h1 = *(const float4*)(hp + 1 * 516 + k);
                const float4 h2 = *(const float4*)(hp + 2 * 516 + k);
                const float4 h3 = *(const float4*)(hp + 3 * 516 + k);
#pragma unroll
                for (int j = 0; j < 4; j++) {
                    const float w0j = (&w0.x)[j], w1j = (&w1.x)[j];
                    const float w2j = (&w2.x)[j], w3j = (&w3.x)[j];
                    acc[0][j] += h0.x * w0j + h0.y * w1j + h0.z * w2j + h0.w * w3j;
                    acc[1][j] += h1.x * w0j + h1.y * w1j + h1.z * w2j + h1.w * w3j;
                    acc[2][j] += h2.x * w0j + h2.y * w1j + h2.z * w2j + h2.w * w3j;
                    acc[3][j] += h3.x * w0j + h3.y * w1j + h3.z * w2j + h3.w * w3j;
                }
            }

            // scatter partials: red[kq][ (r0+i)*64 + c0 .. +3 ]  (STS.128)
            float* rp = red + kq * 512 + r0 * 64 + c0;
#pragma unroll
            for (int i = 0; i < 4; i++)
                *(float4*)(rp + i * 64) = *(float4*)acc[i];
            __syncthreads();

            // reduce over kq for this thread's two outputs (orow, oc/oc+1)
            const float* q = red + orow * 64 + oc;
            float a0 = 0.f, a1 = 0.f;
#pragma unroll
            for (int z = 0; z < 8; z++) {
                const float2 p = *(const float2*)(q + z * 512);
                a0 += p.x; a1 += p.y;
            }
            v0 = tanhf(a0 + xav.x + bg.x);
            v1 = tanhf(a1 + xav.y + bg.y);
        }

        // publish h for next step (straight to L2)
        {
            float2 hv; hv.x = v0; hv.y = v1;
            float2* hdst = (float2*)&g_h[(s + 1) & 1][(size_t)grow * HH + gcol];
            asm volatile("st.global.cg.v2.f32 [%0], {%1, %2};"
                         :: "l"(hdst), "f"(v0), "f"(v1));
        }
        __syncthreads();

        // group barrier arrival (release publishes this step's h writes)
        if (tid == 0) {
            unsigned old;
            asm volatile("atom.add.release.gpu.u32 %0, [%1], %2;"
                         : "=r"(old) : "l"(cnt), "r"(1u));
            if (old == GRP - 1u) {
                asm volatile("st.relaxed.gpu.u32 [%0], %1;"
                             :: "l"(cnt), "r"(0u));
                asm volatile("st.release.gpu.u32 [%0], %1;"
                             :: "l"(sns), "r"(sense ^ 1u));
            }
        }
        sense ^= 1u;

        // epilogue overlaps peers' spin: y writes + next xa prefetch
        {
            float2 yv; yv.x = v0; yv.y = v1;
            *(float2*)&out[(((size_t)b_idx * SS + s) * LL + l_idx) * HH + gcol] = yv;
            if (s == SS - 1) {
                *(float2*)&out[Y_ELEMS + (size_t)grow * HH + gcol] = yv;
            } else {
                xav = *(const float2*)&g_xa[((size_t)b_idx * SS + (s + 1)) * HH + gcol];
            }
        }
    }
}

// =============================================================================
// launch
// =============================================================================
extern "C" void kernel_launch(void* const* d_in, const int* in_sizes, int n_in,
                              void* d_out, int out_size)
{
    const float* x    = (const float*)d_in[0];
    const float* W_ih = (const float*)d_in[1];
    const float* b_ih = (const float*)d_in[2];
    const float* W_hh = (const float*)d_in[3];
    const float* b_hh = (const float*)d_in[4];
    float* out = (float*)d_out;

    // Kernel A: xa = x @ W_ih^T + b_ih
    dim3 gridA(HH / 128, MX / 128);
    gemm_xa_kernel<<<gridA, 256>>>(x, W_ih, b_ih);

    // Kernel B: persistent recurrence
    const int smemB = (512 * 64 + 8 * 516 + 8 * 512) * (int)sizeof(float);
    cudaFuncSetAttribute(rnn_persistent_kernel,
                         cudaFuncAttributeMaxDynamicSharedMemorySize, smemB);
    rnn_persistent_kernel<<<GB_CTAS, 256, smemB>>>(W_hh, b_hh, out);
}